// round 10
// baseline (speedup 1.0000x reference)
#include <cuda_runtime.h>
#include <math_constants.h>
#include <cstdint>

// ---------------- problem constants ----------------
#define PB 8192      // batch rows
#define PK 8192      // codebook size
#define PD 512       // dim per codebook
#define LDZ 1024     // z_e_x row stride (2*PD)
#define LDSC 16384   // scores row stride (2*PK)

// ---------------- GEMM tiling ----------------
#define BM 128
#define BN 128
#define BK 32
#define NK (PD / BK)     // 16 k-iterations
#define NSTG 3           // cp.async pipeline depth
#define NTILE (PK / BN)  // 64 column tiles per codebook

// smem: bf16 tiles [row][k], 64B payload padded to 80B (20-word stride ->
// 8 consecutive rows hit word-banks {0,20,8,28,16,4,24,12}+c : conflict-free)
#define ROWB 80
#define T_BYTES (128 * ROWB)      // 10240 per tile buffer
#define STG_BYTES (4 * T_BYTES)   // AH, AL, BH, BL = 40960
#define SMEM_TOTAL (NSTG * STG_BYTES)  // 122880
#define OFF_AH 0
#define OFF_AL (T_BYTES)
#define OFF_BH (2 * T_BYTES)
#define OFF_BL (3 * T_BYTES)

// ---------------- device scratch ----------------
__device__ uint16_t g_Zh[(size_t)PB * LDZ];
__device__ uint16_t g_Zl[(size_t)PB * LDZ];
__device__ uint16_t g_Wh[(size_t)2 * PK * PD];
__device__ uint16_t g_Wl[(size_t)2 * PK * PD];
// per-(row, codebook, column-tile) argmax candidate: (ord(score)<<32) | ~col
__device__ unsigned long long g_cand[(size_t)PB * 2 * NTILE];   // 8 MB

// ---------------- helpers ----------------
static __device__ __forceinline__ uint32_t pack_bf16(float lo, float hi) {
    uint32_t r;
    asm("cvt.rn.bf16x2.f32 %0, %1, %2;" : "=r"(r) : "f"(hi), "f"(lo));
    return r;
}
static __device__ __forceinline__ void mma16816(float* c, const uint32_t* a, const uint32_t* b) {
    asm volatile(
        "mma.sync.aligned.m16n8k16.row.col.f32.bf16.bf16.f32 "
        "{%0,%1,%2,%3}, {%4,%5,%6,%7}, {%8,%9}, {%0,%1,%2,%3};"
        : "+f"(c[0]), "+f"(c[1]), "+f"(c[2]), "+f"(c[3])
        : "r"(a[0]), "r"(a[1]), "r"(a[2]), "r"(a[3]), "r"(b[0]), "r"(b[1]));
}
static __device__ __forceinline__ uint32_t smem_u32(const void* p) {
    uint32_t a;
    asm("{ .reg .u64 t; cvta.to.shared.u64 t, %1; cvt.u32.u64 %0, t; }" : "=r"(a) : "l"(p));
    return a;
}
static __device__ __forceinline__ uint64_t glob_u64(const void* p) {
    uint64_t a;
    asm("cvta.to.global.u64 %0, %1;" : "=l"(a) : "l"(p));
    return a;
}
#define LDSM4(r, a)                                                           \
    asm volatile("ldmatrix.sync.aligned.m8n8.x4.shared.b16 {%0,%1,%2,%3}, [%4];" \
                 : "=r"((r)[0]), "=r"((r)[1]), "=r"((r)[2]), "=r"((r)[3]) : "r"(a))
#define CP16(dst, src) \
    asm volatile("cp.async.cg.shared.global [%0], [%1], 16;" :: "r"(dst), "l"(src))
#define CP_COMMIT() asm volatile("cp.async.commit_group;" ::: "memory")
#define CP_WAIT1()  asm volatile("cp.async.wait_group 1;" ::: "memory")

static __device__ __forceinline__ unsigned long long score_key(float v, int col) {
    uint32_t u = __float_as_uint(v);
    u = (u & 0x80000000u) ? ~u : (u | 0x80000000u);
    return ((unsigned long long)u << 32) | (uint32_t)(~col);
}
static __device__ __forceinline__ unsigned long long kmax(unsigned long long a,
                                                          unsigned long long b) {
    return a > b ? a : b;
}

// ---------------------------------------------------------------------------
// Kernel 0: split f32 -> bf16 hi + bf16 lo residual.
// ---------------------------------------------------------------------------
__global__ __launch_bounds__(256)
void split_kernel(const float* __restrict__ Z,
                  const float* __restrict__ Wa,
                  const float* __restrict__ Wv)
{
    const int region = blockIdx.y;
    const size_t i = ((size_t)blockIdx.x * 256 + threadIdx.x);   // quad index
    const size_t nquads = (region == 0) ? ((size_t)PB * LDZ / 4) : ((size_t)PK * PD / 4);
    if (i >= nquads) return;

    const float* src;
    uint16_t *dh, *dl;
    if (region == 0)      { src = Z;  dh = g_Zh; dl = g_Zl; }
    else if (region == 1) { src = Wa; dh = g_Wh; dl = g_Wl; }
    else                  { src = Wv; dh = g_Wh + (size_t)PK * PD; dl = g_Wl + (size_t)PK * PD; }

    float4 v = *(const float4*)(src + 4 * i);
    uint32_t h0 = pack_bf16(v.x, v.y);
    uint32_t h1 = pack_bf16(v.z, v.w);
    float r0 = v.x - __uint_as_float(h0 << 16);
    float r1 = v.y - __uint_as_float(h0 & 0xFFFF0000u);
    float r2 = v.z - __uint_as_float(h1 << 16);
    float r3 = v.w - __uint_as_float(h1 & 0xFFFF0000u);
    ((uint2*)dh)[i] = make_uint2(h0, h1);
    ((uint2*)dl)[i] = make_uint2(pack_bf16(r0, r1), pack_bf16(r2, r3));
}

// ---------------------------------------------------------------------------
// Kernel 1: split-bf16 (3-term) mma.sync dual-GEMM, ldmatrix + cp.async,
// BK=32, fused per-tile argmax candidates in the epilogue.
// ---------------------------------------------------------------------------
__global__ __launch_bounds__(256, 1)
void vq_gemm_cp(float* __restrict__ scores)
{
    extern __shared__ __align__(16) char sm[];
    const uint32_t sb = smem_u32(sm);

    const int tid  = threadIdx.x;
    const int lane = tid & 31;
    const int w    = tid >> 5;
    const int wm   = w >> 2;   // 0..1 -> 64-row slab
    const int wn   = w & 3;    // 0..3 -> 32-col slab
    const int g    = blockIdx.z;
    const int bm   = blockIdx.y * BM;
    const int bn   = blockIdx.x * BN;

    // ---- cp.async loader mapping: thread -> row tid>>1, 32B half tid&1 ----
    const int lr = tid >> 1;
    const int kh = tid & 1;
    const uint64_t srcAH = glob_u64(g_Zh + (size_t)(bm + lr) * LDZ + g * PD + kh * 16);
    const uint64_t srcAL = glob_u64(g_Zl + (size_t)(bm + lr) * LDZ + g * PD + kh * 16);
    const uint64_t srcBH = glob_u64(g_Wh + ((size_t)g * PK + bn + lr) * PD + kh * 16);
    const uint64_t srcBL = glob_u64(g_Wl + ((size_t)g * PK + bn + lr) * PD + kh * 16);
    const uint32_t doff = (uint32_t)(lr * ROWB + kh * 32);

    // ---- ldmatrix lane offsets ----
    const int lg  = lane >> 3;
    const int lr8 = lane & 7;
    const uint32_t a_lane = (uint32_t)((((lg & 1) * 8 + lr8) + wm * 64) * ROWB + (lg >> 1) * 16);
    const uint32_t b_lane = (uint32_t)((((lg >> 1) * 8 + lr8) + wn * 32) * ROWB + (lg & 1) * 16);

    const int qr = lane >> 2;        // 0..7
    const int qi = lane & 3;         // 0..3

    float acc[4][4][4];
#pragma unroll
    for (int i = 0; i < 4; i++)
#pragma unroll
        for (int j = 0; j < 4; j++)
#pragma unroll
            for (int q = 0; q < 4; q++) acc[i][j][q] = 0.f;

#define ISSUE(slot, kt_) do {                                            \
    const uint32_t st_ = sb + (slot) * STG_BYTES + doff;                 \
    const uint64_t kb_ = (uint64_t)(kt_) * 64;  /* 32 elems * 2B */      \
    CP16(st_ + OFF_AH, srcAH + kb_);  CP16(st_ + OFF_AH + 16, srcAH + kb_ + 16); \
    CP16(st_ + OFF_AL, srcAL + kb_);  CP16(st_ + OFF_AL + 16, srcAL + kb_ + 16); \
    CP16(st_ + OFF_BH, srcBH + kb_);  CP16(st_ + OFF_BH + 16, srcBH + kb_ + 16); \
    CP16(st_ + OFF_BL, srcBL + kb_);  CP16(st_ + OFF_BL + 16, srcBL + kb_ + 16); \
} while (0)

    ISSUE(0, 0); CP_COMMIT();
    ISSUE(1, 1); CP_COMMIT();

    int sc = 0, si = 2;
    for (int kt = 0; kt < NK; kt++) {
        CP_WAIT1();
        __syncthreads();

        if (kt + 2 < NK) ISSUE(si, kt + 2);
        CP_COMMIT();
        if (++si == NSTG) si = 0;

        const uint32_t stg = sb + sc * STG_BYTES;
        if (++sc == NSTG) sc = 0;

#pragma unroll
        for (int slab = 0; slab < 2; slab++) {
            const uint32_t ks = slab * 32;   // 16 bf16 = 32B
            uint32_t ah[4][4], al[4][4], bb_h[2][4], bb_l[2][4];
#pragma unroll
            for (int mt = 0; mt < 4; mt++) {
                const uint32_t ab = stg + (uint32_t)(mt * 16 * ROWB) + a_lane + ks;
                LDSM4(ah[mt], ab + OFF_AH);
                LDSM4(al[mt], ab + OFF_AL);
            }
#pragma unroll
            for (int p = 0; p < 2; p++) {
                const uint32_t bbase = stg + (uint32_t)(p * 16 * ROWB) + b_lane + ks;
                LDSM4(bb_h[p], bbase + OFF_BH);   // regs 0,1: nt=2p ; 2,3: nt=2p+1
                LDSM4(bb_l[p], bbase + OFF_BL);
            }
            // ---- 3 cross terms; same-acc reuse distance = 16 MMAs ----
#pragma unroll
            for (int nt = 0; nt < 4; nt++)
#pragma unroll
                for (int mt = 0; mt < 4; mt++)
                    mma16816(acc[mt][nt], ah[mt], &bb_h[nt >> 1][(nt & 1) * 2]);
#pragma unroll
            for (int nt = 0; nt < 4; nt++)
#pragma unroll
                for (int mt = 0; mt < 4; mt++)
                    mma16816(acc[mt][nt], al[mt], &bb_h[nt >> 1][(nt & 1) * 2]);
#pragma unroll
            for (int nt = 0; nt < 4; nt++)
#pragma unroll
                for (int mt = 0; mt < 4; mt++)
                    mma16816(acc[mt][nt], ah[mt], &bb_l[nt >> 1][(nt & 1) * 2]);
        }
    }
#undef ISSUE

    // ---- epilogue: write scores + per-row argmax candidate for this tile ----
    __syncthreads();                       // smem pipeline done -> reuse for reduction
    unsigned long long* red = (unsigned long long*)sm;   // [128][4]

    const size_t gcol = (size_t)g * PK + bn;
#pragma unroll
    for (int mt = 0; mt < 4; mt++) {
        const int rl0 = wm * 64 + mt * 16 + qr;          // local rows rl0, rl0+8
        const int r0  = bm + rl0;
        unsigned long long k0 = 0, k1 = 0;
#pragma unroll
        for (int nt = 0; nt < 4; nt++) {
            const int c0 = wn * 32 + nt * 8 + qi * 2;    // col within tile
            float2 lo = make_float2(acc[mt][nt][0], acc[mt][nt][1]);
            float2 hi = make_float2(acc[mt][nt][2], acc[mt][nt][3]);
            *(float2*)(scores + (size_t)r0 * LDSC + gcol + c0)       = lo;
            *(float2*)(scores + (size_t)(r0 + 8) * LDSC + gcol + c0) = hi;
            const int gc = bn + c0;                      // global col in codebook
            k0 = kmax(k0, kmax(score_key(lo.x, gc), score_key(lo.y, gc + 1)));
            k1 = kmax(k1, kmax(score_key(hi.x, gc), score_key(hi.y, gc + 1)));
        }
        // quad reduce (lanes qi=0..3 hold the same rows)
#pragma unroll
        for (int m = 1; m <= 2; m <<= 1) {
            k0 = kmax(k0, __shfl_xor_sync(0xFFFFFFFFu, k0, m));
            k1 = kmax(k1, __shfl_xor_sync(0xFFFFFFFFu, k1, m));
        }
        if (qi == 0) {
            red[(size_t)rl0 * 4 + wn]       = k0;
            red[(size_t)(rl0 + 8) * 4 + wn] = k1;
        }
    }
    __syncthreads();
    if (tid < 128) {
        unsigned long long k = kmax(kmax(red[tid * 4 + 0], red[tid * 4 + 1]),
                                    kmax(red[tid * 4 + 2], red[tid * 4 + 3]));
        g_cand[(((size_t)(bm + tid)) * 2 + g) * NTILE + blockIdx.x] = k;
    }
}

// ---------------------------------------------------------------------------
// Kernel 2: final reduce over 64 tile candidates + gather W[idx].
// ---------------------------------------------------------------------------
__global__ __launch_bounds__(128)
void vq_reduce_gather(const float* __restrict__ Wa,
                      const float* __restrict__ Wv,
                      float* __restrict__ out_st,
                      float* __restrict__ out_q)
{
    const int r = blockIdx.x;
    const int g = blockIdx.y;
    const int tid = threadIdx.x;

    __shared__ unsigned long long s[64];
    __shared__ int s_idx;
    if (tid < 64) s[tid] = g_cand[(((size_t)r) * 2 + g) * NTILE + tid];
    __syncthreads();
    if (tid < 32) {
        unsigned long long k = kmax(s[tid], s[tid + 32]);
#pragma unroll
        for (int off = 16; off > 0; off >>= 1)
            k = kmax(k, __shfl_down_sync(0xFFFFFFFFu, k, off));
        if (tid == 0) s_idx = (int)(~(uint32_t)k);
    }
    __syncthreads();
    const int idx = s_idx;

    const float* __restrict__ Wrow = (g ? Wv : Wa) + (size_t)idx * PD;
    float* st = out_st + (size_t)r * LDZ + (size_t)g * PD;
    float* q  = out_q  + (size_t)r * LDZ + (size_t)g * PD;
    float4 wv = *(const float4*)(Wrow + tid * 4);   // 128 threads x 4 = 512
    *(float4*)(st + tid * 4) = wv;
    *(float4*)(q  + tid * 4) = wv;
}

// ---------------------------------------------------------------------------
// Harness entry
// ---------------------------------------------------------------------------
extern "C" void kernel_launch(void* const* d_in, const int* in_sizes, int n_in,
                              void* d_out, int out_size)
{
    const float* Z  = (const float*)d_in[0];  // [8192, 1024]
    const float* Wa = (const float*)d_in[1];  // [8192, 512]
    const float* Wv = (const float*)d_in[2];  // [8192, 512]

    float* out    = (float*)d_out;
    float* out_st = out;                         // [B, 2D]
    float* out_q  = out + (size_t)PB * LDZ;      // [B, 2D]
    float* scores = out + (size_t)2 * PB * LDZ;  // [B, 2K]

    static int smem_set = 0;
    if (!smem_set) {
        cudaFuncSetAttribute(vq_gemm_cp, cudaFuncAttributeMaxDynamicSharedMemorySize,
                             SMEM_TOTAL);
        smem_set = 1;
    }

    dim3 sgrid((unsigned)(((size_t)PB * LDZ / 4 + 255) / 256), 3);
    split_kernel<<<sgrid, 256>>>(Z, Wa, Wv);

    dim3 ggrid(PK / BN, PB / BM, 2);   // (64, 64, 2)
    vq_gemm_cp<<<ggrid, 256, SMEM_TOTAL>>>(scores);

    dim3 agrid(PB, 2);
    vq_reduce_gather<<<agrid, 128>>>(Wa, Wv, out_st, out_q);
}

// round 11
// speedup vs baseline: 1.0321x; 1.0321x over previous
#include <cuda_runtime.h>
#include <math_constants.h>
#include <cstdint>

// ---------------- problem constants ----------------
#define PB 8192      // batch rows
#define PK 8192      // codebook size
#define PD 512       // dim per codebook
#define LDZ 1024     // z_e_x row stride (2*PD)
#define LDSC 16384   // scores row stride (2*PK)

// ---------------- GEMM tiling (Round-8 proven config) ----------------
#define BM 128
#define BN 128
#define BK 16
#define NK (PD / BK)     // 32 k-iterations
#define NSTG 3           // cp.async pipeline depth
#define NTILE (PK / BN)  // 64 column tiles per codebook

// smem: bf16 tiles [row][k], 32B payload padded to 48B (12-word stride ->
// perfect 32-bank permutation for the 8x4 fragment access pattern)
#define ROWB 48
#define T_BYTES (128 * ROWB)      // 6144 per tile buffer
#define STG_BYTES (4 * T_BYTES)   // AH, AL, BH, BL = 24576
#define SMEM_TOTAL (NSTG * STG_BYTES)  // 73728 -> 2 CTAs/SM fit (147KB < 228KB)
#define OFF_AH 0
#define OFF_AL (T_BYTES)
#define OFF_BH (2 * T_BYTES)
#define OFF_BL (3 * T_BYTES)

// ---------------- device scratch ----------------
__device__ uint16_t g_Zh[(size_t)PB * LDZ];
__device__ uint16_t g_Zl[(size_t)PB * LDZ];
__device__ uint16_t g_Wh[(size_t)2 * PK * PD];
__device__ uint16_t g_Wl[(size_t)2 * PK * PD];
// per-(row, codebook, column-tile) argmax candidate: (ord(score)<<32) | ~col
__device__ unsigned long long g_cand[(size_t)PB * 2 * NTILE];   // 8 MB

// ---------------- helpers ----------------
static __device__ __forceinline__ uint32_t pack_bf16(float lo, float hi) {
    uint32_t r;
    asm("cvt.rn.bf16x2.f32 %0, %1, %2;" : "=r"(r) : "f"(hi), "f"(lo));
    return r;
}
static __device__ __forceinline__ void mma16816(float* c, const uint32_t* a, const uint32_t* b) {
    asm volatile(
        "mma.sync.aligned.m16n8k16.row.col.f32.bf16.bf16.f32 "
        "{%0,%1,%2,%3}, {%4,%5,%6,%7}, {%8,%9}, {%0,%1,%2,%3};"
        : "+f"(c[0]), "+f"(c[1]), "+f"(c[2]), "+f"(c[3])
        : "r"(a[0]), "r"(a[1]), "r"(a[2]), "r"(a[3]), "r"(b[0]), "r"(b[1]));
}
static __device__ __forceinline__ uint32_t smem_u32(const void* p) {
    uint32_t a;
    asm("{ .reg .u64 t; cvta.to.shared.u64 t, %1; cvt.u32.u64 %0, t; }" : "=r"(a) : "l"(p));
    return a;
}
static __device__ __forceinline__ uint64_t glob_u64(const void* p) {
    uint64_t a;
    asm("cvta.to.global.u64 %0, %1;" : "=l"(a) : "l"(p));
    return a;
}
#define CP16(dst, src) \
    asm volatile("cp.async.cg.shared.global [%0], [%1], 16;" :: "r"(dst), "l"(src))
#define CP_COMMIT() asm volatile("cp.async.commit_group;" ::: "memory")
#define CP_WAIT1()  asm volatile("cp.async.wait_group 1;" ::: "memory")

static __device__ __forceinline__ unsigned long long score_key(float v, int col) {
    uint32_t u = __float_as_uint(v);
    u = (u & 0x80000000u) ? ~u : (u | 0x80000000u);
    return ((unsigned long long)u << 32) | (uint32_t)(~col);
}
static __device__ __forceinline__ unsigned long long kmax(unsigned long long a,
                                                          unsigned long long b) {
    return a > b ? a : b;
}

// ---------------------------------------------------------------------------
// Kernel 0: split f32 -> bf16 hi + bf16 lo residual.
// ---------------------------------------------------------------------------
__global__ __launch_bounds__(256)
void split_kernel(const float* __restrict__ Z,
                  const float* __restrict__ Wa,
                  const float* __restrict__ Wv)
{
    const int region = blockIdx.y;
    const size_t i = ((size_t)blockIdx.x * 256 + threadIdx.x);   // quad index
    const size_t nquads = (region == 0) ? ((size_t)PB * LDZ / 4) : ((size_t)PK * PD / 4);
    if (i >= nquads) return;

    const float* src;
    uint16_t *dh, *dl;
    if (region == 0)      { src = Z;  dh = g_Zh; dl = g_Zl; }
    else if (region == 1) { src = Wa; dh = g_Wh; dl = g_Wl; }
    else                  { src = Wv; dh = g_Wh + (size_t)PK * PD; dl = g_Wl + (size_t)PK * PD; }

    float4 v = *(const float4*)(src + 4 * i);
    uint32_t h0 = pack_bf16(v.x, v.y);
    uint32_t h1 = pack_bf16(v.z, v.w);
    float r0 = v.x - __uint_as_float(h0 << 16);
    float r1 = v.y - __uint_as_float(h0 & 0xFFFF0000u);
    float r2 = v.z - __uint_as_float(h1 << 16);
    float r3 = v.w - __uint_as_float(h1 & 0xFFFF0000u);
    ((uint2*)dh)[i] = make_uint2(h0, h1);
    ((uint2*)dl)[i] = make_uint2(pack_bf16(r0, r1), pack_bf16(r2, r3));
}

// ---------------------------------------------------------------------------
// Kernel 1: split-bf16 (3-term) mma.sync dual-GEMM. Round-8 mainloop
// (BK=16, scalar LDS frags, cp.async 3-stage) + fused argmax epilogue.
// __launch_bounds__(256, 2): target 128 regs -> 2 CTAs/SM to hide
// per-iteration pipeline bubbles across CTAs.
// ---------------------------------------------------------------------------
__global__ __launch_bounds__(256, 2)
void vq_gemm_cp(float* __restrict__ scores)
{
    extern __shared__ __align__(16) char sm[];
    const uint32_t sb = smem_u32(sm);

    const int tid  = threadIdx.x;
    const int lane = tid & 31;
    const int w    = tid >> 5;
    const int wm   = w >> 2;   // 0..1 -> 64-row slab
    const int wn   = w & 3;    // 0..3 -> 32-col slab
    const int g    = blockIdx.z;
    const int bm   = blockIdx.y * BM;
    const int bn   = blockIdx.x * BN;

    // loader mapping: thread covers row tid>>1, 16B chunk (tid&1) of the 32B row
    const int lr = tid >> 1;
    const int kh = tid & 1;
    const uint64_t srcAH = glob_u64(g_Zh + (size_t)(bm + lr) * LDZ + g * PD + kh * 8);
    const uint64_t srcAL = glob_u64(g_Zl + (size_t)(bm + lr) * LDZ + g * PD + kh * 8);
    const uint64_t srcBH = glob_u64(g_Wh + ((size_t)g * PK + bn + lr) * PD + kh * 8);
    const uint64_t srcBL = glob_u64(g_Wl + ((size_t)g * PK + bn + lr) * PD + kh * 8);
    const uint32_t doff = (uint32_t)(lr * ROWB + kh * 16);

    const int qr = lane >> 2;        // 0..7
    const int qi = lane & 3;         // 0..3
    const int qc = qi * 4;           // word byte-offset 0..12

    float acc[4][4][4];
#pragma unroll
    for (int i = 0; i < 4; i++)
#pragma unroll
        for (int j = 0; j < 4; j++)
#pragma unroll
            for (int q = 0; q < 4; q++) acc[i][j][q] = 0.f;

#define ISSUE(slot, kt_) do {                                            \
    const uint32_t st_ = sb + (slot) * STG_BYTES + doff;                 \
    const uint64_t kb_ = (uint64_t)(kt_) * 32;  /* 16 elems * 2B */      \
    CP16(st_ + OFF_AH, srcAH + kb_);                                     \
    CP16(st_ + OFF_AL, srcAL + kb_);                                     \
    CP16(st_ + OFF_BH, srcBH + kb_);                                     \
    CP16(st_ + OFF_BL, srcBL + kb_);                                     \
} while (0)

    ISSUE(0, 0); CP_COMMIT();
    ISSUE(1, 1); CP_COMMIT();

    int sc = 0, si = 2;
    for (int kt = 0; kt < NK; kt++) {
        CP_WAIT1();
        __syncthreads();

        if (kt + 2 < NK) ISSUE(si, kt + 2);
        CP_COMMIT();
        if (++si == NSTG) si = 0;

        const char* stg = sm + sc * STG_BYTES;
        if (++sc == NSTG) sc = 0;

        // ---- fragment loads (LDS.b32, conflict-free via 48B row stride) ----
        uint32_t ah[4][4], al[4][4], bh[4][2], bl[4][2];
#pragma unroll
        for (int mt = 0; mt < 4; mt++) {
            const int m0 = (wm * 64 + mt * 16 + qr) * ROWB + qc;
            const int m8 = m0 + 8 * ROWB;
            ah[mt][0] = *(const uint32_t*)(stg + OFF_AH + m0);
            ah[mt][1] = *(const uint32_t*)(stg + OFF_AH + m8);
            ah[mt][2] = *(const uint32_t*)(stg + OFF_AH + m0 + 16);
            ah[mt][3] = *(const uint32_t*)(stg + OFF_AH + m8 + 16);
            al[mt][0] = *(const uint32_t*)(stg + OFF_AL + m0);
            al[mt][1] = *(const uint32_t*)(stg + OFF_AL + m8);
            al[mt][2] = *(const uint32_t*)(stg + OFF_AL + m0 + 16);
            al[mt][3] = *(const uint32_t*)(stg + OFF_AL + m8 + 16);
        }
#pragma unroll
        for (int nt = 0; nt < 4; nt++) {
            const int n0 = (wn * 32 + nt * 8 + qr) * ROWB + qc;
            bh[nt][0] = *(const uint32_t*)(stg + OFF_BH + n0);
            bh[nt][1] = *(const uint32_t*)(stg + OFF_BH + n0 + 16);
            bl[nt][0] = *(const uint32_t*)(stg + OFF_BL + n0);
            bl[nt][1] = *(const uint32_t*)(stg + OFF_BL + n0 + 16);
        }

        // ---- 3 cross terms; same-acc reuse distance = 16 MMAs ----
#pragma unroll
        for (int nt = 0; nt < 4; nt++)
#pragma unroll
            for (int mt = 0; mt < 4; mt++) mma16816(acc[mt][nt], ah[mt], bh[nt]);
#pragma unroll
        for (int nt = 0; nt < 4; nt++)
#pragma unroll
            for (int mt = 0; mt < 4; mt++) mma16816(acc[mt][nt], al[mt], bh[nt]);
#pragma unroll
        for (int nt = 0; nt < 4; nt++)
#pragma unroll
            for (int mt = 0; mt < 4; mt++) mma16816(acc[mt][nt], ah[mt], bl[nt]);
    }
#undef ISSUE

    // ---- epilogue: write scores + per-row argmax candidate for this tile ----
    __syncthreads();                       // smem pipeline done -> reuse for reduction
    unsigned long long* red = (unsigned long long*)sm;   // [128][4]

    const size_t gcol = (size_t)g * PK + bn;
#pragma unroll
    for (int mt = 0; mt < 4; mt++) {
        const int rl0 = wm * 64 + mt * 16 + qr;          // local rows rl0, rl0+8
        const int r0  = bm + rl0;
        unsigned long long k0 = 0, k1 = 0;
#pragma unroll
        for (int nt = 0; nt < 4; nt++) {
            const int c0 = wn * 32 + nt * 8 + qi * 2;    // col within tile
            float2 lo = make_float2(acc[mt][nt][0], acc[mt][nt][1]);
            float2 hi = make_float2(acc[mt][nt][2], acc[mt][nt][3]);
            *(float2*)(scores + (size_t)r0 * LDSC + gcol + c0)       = lo;
            *(float2*)(scores + (size_t)(r0 + 8) * LDSC + gcol + c0) = hi;
            const int gc = bn + c0;                      // global col in codebook
            k0 = kmax(k0, kmax(score_key(lo.x, gc), score_key(lo.y, gc + 1)));
            k1 = kmax(k1, kmax(score_key(hi.x, gc), score_key(hi.y, gc + 1)));
        }
        // quad reduce (lanes qi=0..3 hold the same rows)
#pragma unroll
        for (int m = 1; m <= 2; m <<= 1) {
            k0 = kmax(k0, __shfl_xor_sync(0xFFFFFFFFu, k0, m));
            k1 = kmax(k1, __shfl_xor_sync(0xFFFFFFFFu, k1, m));
        }
        if (qi == 0) {
            red[(size_t)rl0 * 4 + wn]       = k0;
            red[(size_t)(rl0 + 8) * 4 + wn] = k1;
        }
    }
    __syncthreads();
    if (tid < 128) {
        unsigned long long k = kmax(kmax(red[tid * 4 + 0], red[tid * 4 + 1]),
                                    kmax(red[tid * 4 + 2], red[tid * 4 + 3]));
        g_cand[(((size_t)(bm + tid)) * 2 + g) * NTILE + blockIdx.x] = k;
    }
}

// ---------------------------------------------------------------------------
// Kernel 2: final reduce over 64 tile candidates + gather W[idx].
// ---------------------------------------------------------------------------
__global__ __launch_bounds__(128)
void vq_reduce_gather(const float* __restrict__ Wa,
                      const float* __restrict__ Wv,
                      float* __restrict__ out_st,
                      float* __restrict__ out_q)
{
    const int r = blockIdx.x;
    const int g = blockIdx.y;
    const int tid = threadIdx.x;

    __shared__ unsigned long long s[64];
    __shared__ int s_idx;
    if (tid < 64) s[tid] = g_cand[(((size_t)r) * 2 + g) * NTILE + tid];
    __syncthreads();
    if (tid < 32) {
        unsigned long long k = kmax(s[tid], s[tid + 32]);
#pragma unroll
        for (int off = 16; off > 0; off >>= 1)
            k = kmax(k, __shfl_down_sync(0xFFFFFFFFu, k, off));
        if (tid == 0) s_idx = (int)(~(uint32_t)k);
    }
    __syncthreads();
    const int idx = s_idx;

    const float* __restrict__ Wrow = (g ? Wv : Wa) + (size_t)idx * PD;
    float* st = out_st + (size_t)r * LDZ + (size_t)g * PD;
    float* q  = out_q  + (size_t)r * LDZ + (size_t)g * PD;
    float4 wv = *(const float4*)(Wrow + tid * 4);   // 128 threads x 4 = 512
    *(float4*)(st + tid * 4) = wv;
    *(float4*)(q  + tid * 4) = wv;
}

// ---------------------------------------------------------------------------
// Harness entry
// ---------------------------------------------------------------------------
extern "C" void kernel_launch(void* const* d_in, const int* in_sizes, int n_in,
                              void* d_out, int out_size)
{
    const float* Z  = (const float*)d_in[0];  // [8192, 1024]
    const float* Wa = (const float*)d_in[1];  // [8192, 512]
    const float* Wv = (const float*)d_in[2];  // [8192, 512]

    float* out    = (float*)d_out;
    float* out_st = out;                         // [B, 2D]
    float* out_q  = out + (size_t)PB * LDZ;      // [B, 2D]
    float* scores = out + (size_t)2 * PB * LDZ;  // [B, 2K]

    static int smem_set = 0;
    if (!smem_set) {
        cudaFuncSetAttribute(vq_gemm_cp, cudaFuncAttributeMaxDynamicSharedMemorySize,
                             SMEM_TOTAL);
        smem_set = 1;
    }

    dim3 sgrid((unsigned)(((size_t)PB * LDZ / 4 + 255) / 256), 3);
    split_kernel<<<sgrid, 256>>>(Z, Wa, Wv);

    dim3 ggrid(PK / BN, PB / BM, 2);   // (64, 64, 2)
    vq_gemm_cp<<<ggrid, 256, SMEM_TOTAL>>>(scores);

    dim3 agrid(PB, 2);
    vq_reduce_gather<<<agrid, 128>>>(Wa, Wv, out_st, out_q);
}